// round 4
// baseline (speedup 1.0000x reference)
#include <cuda_runtime.h>
#include <math.h>
#include <stdint.h>

// Problem constants
#define L_SEQ 2048
#define B_SZ  32
#define DIN   128
#define DST   512

// Scratch (device globals per allocation rules)
__device__ float g_pre[L_SEQ * B_SZ * DST];   // [l][b][h]   128 MB
__device__ float g_hs [L_SEQ * B_SZ * DST];   // [l][b][h]   128 MB
__device__ float g_xT [L_SEQ * B_SZ * DIN];   // [l][b][d]    32 MB

union F4U  { float4 f4; ulonglong2 u2; };
union U64F { unsigned long long u; float2 f; };

__device__ __forceinline__ void ffma2(unsigned long long& acc,
                                      unsigned long long a,
                                      unsigned long long b) {
    asm volatile("fma.rn.f32x2 %0, %1, %2, %0;" : "+l"(acc) : "l"(a), "l"(b));
}

__device__ __forceinline__ uint32_t smem_u32(const void* p) {
    return (uint32_t)__cvta_generic_to_shared(p);
}

// Hinted (HW-sleep) cluster-scope parity wait — no busy smem-port hammering.
__device__ __forceinline__ void mbar_wait_cluster(uint32_t addr, uint32_t parity) {
    asm volatile(
        "{\n\t"
        ".reg .pred P;\n\t"
        "WAIT%=:\n\t"
        "mbarrier.try_wait.parity.acquire.cluster.shared::cta.b64 P, [%0], %1, 0x989680;\n\t"
        "@P bra DONE%=;\n\t"
        "bra WAIT%=;\n\t"
        "DONE%=:\n\t"
        "}\n"
        :: "r"(addr), "r"(parity) : "memory");
}

// ---------------------------------------------------------------------------
// Kernel 0: transpose x[b][d][l] -> xT[l][b*128+d].  Tiled 32x32, fully
// coalesced both sides (kills the 8x sector-waste gather in k_pre).
// Treat x as a 4096(bd) x 2048(l) row-major matrix.
// ---------------------------------------------------------------------------
__global__ void __launch_bounds__(256) k_xT(const float* __restrict__ x) {
    __shared__ float sm[32 * 33];
    const int l0  = blockIdx.x * 32;
    const int bd0 = blockIdx.y * 32;
    const int t   = threadIdx.x;
    for (int i = t; i < 1024; i += 256) {
        int r = i >> 5, c = i & 31;                 // r: bd, c: l
        sm[r * 33 + c] = x[(size_t)(bd0 + r) * L_SEQ + l0 + c];
    }
    __syncthreads();
    for (int i = t; i < 1024; i += 256) {
        int r = i >> 5, c = i & 31;                 // r: l, c: bd
        g_xT[(size_t)(l0 + r) * (B_SZ * DIN) + bd0 + c] = sm[c * 33 + r];
    }
}

// ---------------------------------------------------------------------------
// Kernel 1: pre[l][b][h] = b_ih[h]+b_hh[h] + sum_d xT[l][b][d] * W_ih[h][d]
// Grid (2048 l, 2 hblk of 256 h). 512 threads. Thread tile: 4 strided h
// (tx+64j, conflict-free scalar LDS) x 4 b (broadcast float4).
// ---------------------------------------------------------------------------
#define PRE_SMEM ((128 * 257 + 128 * 36) * 4)

__global__ void __launch_bounds__(512) k_pre(const float* __restrict__ Wih,
                                             const float* __restrict__ bih,
                                             const float* __restrict__ bhh) {
    extern __shared__ float sm[];
    float* w_s = sm;               // [128 d][257]  (h-slice major, padded)
    float* x_s = sm + 128 * 257;   // [128 d][36]   (b major, padded)

    const int l  = blockIdx.x;
    const int h0 = blockIdx.y * 256;
    const int t  = threadIdx.x;

    for (int idx = t; idx < 256 * 128; idx += 512) {
        int d = idx & 127, hh = idx >> 7;
        w_s[d * 257 + hh] = Wih[(size_t)(h0 + hh) * DIN + d];
    }
    for (int idx = t; idx < B_SZ * DIN; idx += 512) {
        int d = idx & 127, b = idx >> 7;
        x_s[d * 36 + b] = g_xT[(size_t)l * (B_SZ * DIN) + b * DIN + d];
    }
    __syncthreads();

    const int tx = t & 63;
    const int b0 = (t >> 6) * 4;

    unsigned long long acc[2][4];
#pragma unroll
    for (int m = 0; m < 2; m++)
#pragma unroll
        for (int b = 0; b < 4; b++) acc[m][b] = 0ull;

#pragma unroll 4
    for (int k = 0; k < 128; k++) {
        const float* wr = w_s + k * 257 + tx;
        U64F p0, p1;
        p0.f.x = wr[0];   p0.f.y = wr[64];
        p1.f.x = wr[128]; p1.f.y = wr[192];
        F4U xv; xv.f4 = *(const float4*)(x_s + k * 36 + b0);
        float xs[4] = {xv.f4.x, xv.f4.y, xv.f4.z, xv.f4.w};
#pragma unroll
        for (int b = 0; b < 4; b++) {
            U64F d2; d2.f.x = xs[b]; d2.f.y = xs[b];
            ffma2(acc[0][b], p0.u, d2.u);
            ffma2(acc[1][b], p1.u, d2.u);
        }
    }

    float bias[4];
#pragma unroll
    for (int j = 0; j < 4; j++)
        bias[j] = bih[h0 + tx + 64 * j] + bhh[h0 + tx + 64 * j];

#pragma unroll
    for (int b = 0; b < 4; b++) {
        float* pr = g_pre + ((size_t)l * B_SZ + b0 + b) * DST + h0 + tx;
        U64F u0, u1; u0.u = acc[0][b]; u1.u = acc[1][b];
        pr[0]   = u0.f.x + bias[0];
        pr[64]  = u0.f.y + bias[1];
        pr[128] = u1.f.x + bias[2];
        pr[192] = u1.f.y + bias[3];
    }
}

// ---------------------------------------------------------------------------
// Kernel 2: recurrent scan. 16 clusters x 8 CTAs, 512 threads/CTA.
// CTA rank owns h rows [64*rank, +64) for the cluster's 2 batches.
// W_hh slice in registers (64 floats/thread). DSMEM push exchange,
// double-buffered remote mbarriers, HW-sleep hinted waits.
// ---------------------------------------------------------------------------
__global__ void __launch_bounds__(512, 1) __cluster_dims__(8, 1, 1)
k_rnn(const float* __restrict__ Whh) {
    __shared__ float hbuf[2][2 * DST];   // double-buffered full h, 2 batches
    __shared__ float red[8][2][64];      // partials: [kslice][batch][row]
    __shared__ __align__(8) unsigned long long barr[2];

    const int t = threadIdx.x;
    uint32_t rank;
    asm("mov.u32 %0, %%cluster_ctarank;" : "=r"(rank));
    const int cl = blockIdx.x >> 3;      // cluster id 0..15
    const int r  = t & 63;               // row within my 64-row slice
    const int ks = t >> 6;               // K slice 0..7 (64 wide each)

    // W_hh slice -> registers (constant across all steps): 16 float4
    F4U w[16];
    {
        const float4* wp = (const float4*)(Whh + (size_t)(rank * 64 + r) * DST + ks * 64);
#pragma unroll
        for (int i = 0; i < 16; i++) w[i].f4 = wp[i];
    }

    // h_{-1} = 0 lives in buffer 1 (step 0 reads buf[(0-1)&1] = buf[1])
    for (int i = t; i < 2 * DST; i += 512) hbuf[1][i] = 0.f;

    uint32_t bar0 = smem_u32(&barr[0]);
    if (t == 0) {
        asm volatile("mbarrier.init.shared.b64 [%0], %1;" :: "r"(bar0), "r"(8u) : "memory");
        asm volatile("mbarrier.init.shared.b64 [%0], %1;" :: "r"(bar0 + 8), "r"(8u) : "memory");
        asm volatile("fence.mbarrier_init.release.cluster;" ::: "memory");
    }
    __syncthreads();
    asm volatile("barrier.cluster.arrive.aligned;" ::: "memory");
    asm volatile("barrier.cluster.wait.aligned;" ::: "memory");

    const uint32_t hbase = smem_u32(&hbuf[0][0]);
    uint32_t peer_h[8], peer_b[8];
#pragma unroll
    for (int p = 0; p < 8; p++) {
        asm("mapa.shared::cluster.u32 %0, %1, %2;" : "=r"(peer_h[p]) : "r"(hbase), "r"(p));
        asm("mapa.shared::cluster.u32 %0, %1, %2;" : "=r"(peer_b[p]) : "r"(bar0), "r"(p));
    }

    const int b0 = cl * 2;
    const int tb = t >> 6;   // (t<128): batch 0/1
    const int tr = t & 63;   // (t<128): row
    const size_t outoff = (size_t)(b0 + tb) * DST + rank * 64 + tr;

    for (int l = 0; l < L_SEQ; l++) {
        const int cur = l & 1, prev = cur ^ 1;

        // prefetch pre-activation (independent of the barrier)
        float pv = 0.f;
        if (t < 128) pv = __ldg(g_pre + (size_t)l * (B_SZ * DST) + outoff);

        if (l > 0) mbar_wait_cluster(bar0 + 8u * (uint32_t)prev, ((l - 1) >> 1) & 1);

        // partial matvec: rows owned by this CTA, K slice owned by this thread
        const float* hbp = hbuf[prev];
#pragma unroll
        for (int b = 0; b < 2; b++) {
            const float4* hp = (const float4*)(hbp + b * DST + ks * 64);
            unsigned long long a0 = 0ull, a1 = 0ull;
#pragma unroll
            for (int i = 0; i < 16; i++) {
                F4U hv; hv.f4 = hp[i];
                ffma2(a0, hv.u2.x, w[i].u2.x);
                ffma2(a1, hv.u2.y, w[i].u2.y);
            }
            U64F u0, u1; u0.u = a0; u1.u = a1;
            red[ks][b][r] = u0.f.x + u0.f.y + u1.f.x + u1.f.y;
        }
        __syncthreads();

        if (t < 128) {
            float s = pv;
#pragma unroll
            for (int k2 = 0; k2 < 8; k2++) s += red[k2][tb][tr];
            float hv = tanhf(s);
            g_hs[(size_t)l * (B_SZ * DST) + outoff] = hv;
            if (l < L_SEQ - 1) {
                uint32_t off = (uint32_t)((cur * 2 * DST + tb * DST + (int)rank * 64 + tr) * 4);
#pragma unroll
                for (int p = 0; p < 8; p++)
                    asm volatile("st.shared::cluster.f32 [%0], %1;"
                                 :: "r"(peer_h[p] + off), "f"(hv) : "memory");
            }
        }
        __syncthreads();

        if (l < L_SEQ - 1 && t < 8)
            asm volatile("mbarrier.arrive.release.cluster.shared::cluster.b64 _, [%0];"
                         :: "r"(peer_b[t] + 8u * (uint32_t)cur) : "memory");
    }

    // No CTA may exit while peers could still touch its smem.
    asm volatile("barrier.cluster.arrive.aligned;" ::: "memory");
    asm volatile("barrier.cluster.wait.aligned;" ::: "memory");
}

// ---------------------------------------------------------------------------
// Kernel 3: y[lb][o] = tanh(b_fc[o] + sum_k hs[lb][k] * W_fc[o][k])
// 1024 blocks x 512 threads: 64 lb x 128 o per block, K chunked by 128.
// Thread tile: 4 strided o (tx+32j) x 4 lb (broadcast float4).
// ---------------------------------------------------------------------------
#define OUT_SMEM ((128 * 132 + 128 * 68) * 4)

__global__ void __launch_bounds__(512) k_out(const float* __restrict__ Wfc,
                                             const float* __restrict__ bfc,
                                             float* __restrict__ y) {
    extern __shared__ float sm[];
    float* w_s = sm;               // [128 kk][132] (o major, padded)
    float* a_s = sm + 128 * 132;   // [128 kk][68]  (lb major, padded)

    const int t = threadIdx.x;
    const size_t base = (size_t)blockIdx.x * 64;
    const int tx  = t & 31;        // o = tx + 32j
    const int lb0 = (t >> 5) * 4;  // 16 groups x 4 lb

    unsigned long long acc[2][4];
#pragma unroll
    for (int m = 0; m < 2; m++)
#pragma unroll
        for (int b = 0; b < 4; b++) acc[m][b] = 0ull;

    for (int kc = 0; kc < 4; kc++) {
        __syncthreads();
        for (int idx = t; idx < 128 * 128; idx += 512) {
            int kk = idx & 127, o = idx >> 7;
            w_s[kk * 132 + o] = Wfc[(size_t)o * DST + kc * 128 + kk];
        }
        for (int idx = t; idx < 64 * 128; idx += 512) {
            int kk = idx & 127, row = idx >> 7;
            a_s[kk * 68 + row] = g_hs[(base + row) * DST + kc * 128 + kk];
        }
        __syncthreads();

#pragma unroll 4
        for (int k = 0; k < 128; k++) {
            const float* wr = w_s + k * 132 + tx;
            U64F p0, p1;
            p0.f.x = wr[0];  p0.f.y = wr[32];
            p1.f.x = wr[64]; p1.f.y = wr[96];
            F4U av; av.f4 = *(const float4*)(a_s + k * 68 + lb0);
            float as4[4] = {av.f4.x, av.f4.y, av.f4.z, av.f4.w};
#pragma unroll
            for (int b = 0; b < 4; b++) {
                U64F d2; d2.f.x = as4[b]; d2.f.y = as4[b];
                ffma2(acc[0][b], p0.u, d2.u);
                ffma2(acc[1][b], p1.u, d2.u);
            }
        }
    }

    float bias[4];
#pragma unroll
    for (int j = 0; j < 4; j++) bias[j] = bfc[tx + 32 * j];

#pragma unroll
    for (int b = 0; b < 4; b++) {
        float* yp = y + (base + lb0 + b) * DIN + tx;
        U64F u0, u1; u0.u = acc[0][b]; u1.u = acc[1][b];
        yp[0]  = tanhf(u0.f.x + bias[0]);
        yp[32] = tanhf(u0.f.y + bias[1]);
        yp[64] = tanhf(u1.f.x + bias[2]);
        yp[96] = tanhf(u1.f.y + bias[3]);
    }
}

// ---------------------------------------------------------------------------
extern "C" void kernel_launch(void* const* d_in, const int* in_sizes, int n_in,
                              void* d_out, int out_size) {
    const float* x   = (const float*)d_in[0];
    const float* Wih = (const float*)d_in[1];
    const float* Whh = (const float*)d_in[2];
    const float* bih = (const float*)d_in[3];
    const float* bhh = (const float*)d_in[4];
    const float* Wfc = (const float*)d_in[5];
    const float* bfc = (const float*)d_in[6];
    float* y = (float*)d_out;

    cudaFuncSetAttribute(k_pre, cudaFuncAttributeMaxDynamicSharedMemorySize, PRE_SMEM);
    cudaFuncSetAttribute(k_out, cudaFuncAttributeMaxDynamicSharedMemorySize, OUT_SMEM);

    k_xT<<<dim3(L_SEQ / 32, (B_SZ * DIN) / 32), 256>>>(x);
    k_pre<<<dim3(L_SEQ, 2), 512, PRE_SMEM>>>(Wih, bih, bhh);
    k_rnn<<<128, 512>>>(Whh);
    k_out<<<(L_SEQ * B_SZ) / 64, 512, OUT_SMEM>>>(Wfc, bfc, y);
}